// round 1
// baseline (speedup 1.0000x reference)
#include <cuda_runtime.h>
#include <cuda_bf16.h>

// Problem constants
#define BB 8
#define NN 2048
#define DD 256
#define KK 8192
#define M_TOK (BB*NN)          // 16384 tokens

// Tiling
#define BM 64                  // tokens per block
#define BN 64                  // codes per tile
#define BD 64                  // d-chunk per smem stage
#define BS_STRIDE 68           // padded code-row stride (floats), 16B-aligned
#define THREADS 256

__device__ float g_c2[KK];
__device__ int   g_idx[M_TOK];

// ---------------------------------------------------------------------------
// Kernel 1: c2[k] = ||codebook_k||^2  (one warp per code)
// ---------------------------------------------------------------------------
__global__ void c2_kernel(const float* __restrict__ cb) {
    int gwarp = (blockIdx.x * blockDim.x + threadIdx.x) >> 5;
    int lane  = threadIdx.x & 31;
    if (gwarp >= KK) return;
    const float* r = cb + (size_t)gwarp * DD;
    float s = 0.f;
    #pragma unroll
    for (int d = 0; d < DD / 32; d++) {
        float v = r[lane + d * 32];
        s += v * v;
    }
    #pragma unroll
    for (int o = 16; o; o >>= 1) s += __shfl_xor_sync(0xffffffffu, s, o);
    if (lane == 0) g_c2[gwarp] = s;
}

// ---------------------------------------------------------------------------
// Kernel 2: fused distance + argmin.
//   256 blocks x 256 threads. Block owns 64 tokens (full D in smem).
//   Streams codebook in 64-code x 64-d chunks with register prefetch.
//   Thread tile 4 rows (ty*4+i) x 4 cols (tx + 16*j).
//   Scores: s = c2[k] - 2*dot(z, c_k)   (z2 is a per-token constant; argmin
//   ordering is unchanged).
// ---------------------------------------------------------------------------
__global__ void __launch_bounds__(THREADS, 2)
vq_argmin_kernel(const float* __restrict__ x, const float* __restrict__ cb) {
    extern __shared__ float smem[];
    float* Xs = smem;                    // [BM][DD]        = 65536 B
    float* Bs = smem + BM * DD;          // [BN][BS_STRIDE] = 17408 B

    const int tid = threadIdx.x;
    const int tx  = tid & 15;            // code group
    const int ty  = tid >> 4;            // token group
    const int rowBase = blockIdx.x * BM;

    // Load the full X tile (64 tokens x 256 d), float4, coalesced.
    for (int i = tid; i < BM * DD / 4; i += THREADS) {
        int tok = i >> 6;                // 64 float4 per token
        int dg  = i & 63;
        float4 v = __ldg((const float4*)(x + (size_t)(rowBase + tok) * DD + dg * 4));
        *(float4*)(Xs + tok * DD + dg * 4) = v;
    }

    float best[4];
    int   bidx[4];
    #pragma unroll
    for (int i = 0; i < 4; i++) { best[i] = 3.4e38f; bidx[i] = 0; }

    float acc[4][4];

    const int NCHUNK = (KK / BN) * (DD / BD);   // 512 chunks (ct = ci>>2, dc = ci&3)

    // Register prefetch of chunk 0
    float4 pre[4];
    #pragma unroll
    for (int k = 0; k < 4; k++) {
        int i = tid + k * THREADS;
        int code = i >> 4, dg = i & 15;
        pre[k] = __ldg((const float4*)(cb + (size_t)code * DD + dg * 4));
    }

    for (int ci = 0; ci < NCHUNK; ci++) {
        const int dc = ci & 3;

        __syncthreads();   // previous chunk's compute done; Bs free
        #pragma unroll
        for (int k = 0; k < 4; k++) {
            int i = tid + k * THREADS;
            int code = i >> 4, dg = i & 15;
            *(float4*)(Bs + code * BS_STRIDE + dg * 4) = pre[k];
        }
        // Prefetch next chunk (LDG latency overlaps this chunk's compute)
        if (ci + 1 < NCHUNK) {
            int cn = ci + 1;
            int ctn = cn >> 2, dcn = cn & 3;
            #pragma unroll
            for (int k = 0; k < 4; k++) {
                int i = tid + k * THREADS;
                int code = i >> 4, dg = i & 15;
                pre[k] = __ldg((const float4*)(cb + (size_t)(ctn * BN + code) * DD
                                               + dcn * BD + dg * 4));
            }
        }
        if (dc == 0) {
            #pragma unroll
            for (int i = 0; i < 4; i++)
                #pragma unroll
                for (int j = 0; j < 4; j++) acc[i][j] = 0.f;
        }
        __syncthreads();   // Bs filled

        const float* xbase = Xs + dc * BD;
        #pragma unroll
        for (int d4 = 0; d4 < BD; d4 += 4) {
            float4 a[4], b[4];
            #pragma unroll
            for (int i = 0; i < 4; i++)
                a[i] = *(const float4*)(xbase + (ty * 4 + i) * DD + d4);
            #pragma unroll
            for (int j = 0; j < 4; j++)
                b[j] = *(const float4*)(Bs + (tx + j * 16) * BS_STRIDE + d4);
            #pragma unroll
            for (int i = 0; i < 4; i++)
                #pragma unroll
                for (int j = 0; j < 4; j++)
                    acc[i][j] += a[i].x * b[j].x + a[i].y * b[j].y
                               + a[i].z * b[j].z + a[i].w * b[j].w;
        }

        if (dc == 3) {
            const int ct = ci >> 2;
            #pragma unroll
            for (int j = 0; j < 4; j++) {        // ascending column order
                int col   = ct * BN + tx + j * 16;
                float c2v = __ldg(g_c2 + col);
                #pragma unroll
                for (int i = 0; i < 4; i++) {
                    float s = c2v - 2.f * acc[i][j];
                    if (s < best[i]) { best[i] = s; bidx[i] = col; }  // strict < => earliest index wins
                }
            }
        }
    }

    // Cross-thread argmin reduce over the 16 tx-threads per row (alias Bs).
    __syncthreads();
    float* rv = Bs;                       // [BM][16] floats
    int*   ri = (int*)(Bs + BM * 16);     // [BM][16] ints
    #pragma unroll
    for (int i = 0; i < 4; i++) {
        rv[(ty * 4 + i) * 16 + tx] = best[i];
        ri[(ty * 4 + i) * 16 + tx] = bidx[i];
    }
    __syncthreads();
    if (tid < BM) {
        float bv = rv[tid * 16];
        int   bi = ri[tid * 16];
        #pragma unroll
        for (int t = 1; t < 16; t++) {
            float v  = rv[tid * 16 + t];
            int   ii = ri[tid * 16 + t];
            if (v < bv || (v == bv && ii < bi)) { bv = v; bi = ii; }
        }
        g_idx[rowBase + tid] = bi;
    }
}

// ---------------------------------------------------------------------------
// Kernel 3: write outputs. Layout: [x_recon | z_e | z_q | indices(float)]
// ---------------------------------------------------------------------------
__global__ void scatter_kernel(const float* __restrict__ x,
                               const float* __restrict__ cb,
                               float* __restrict__ out) {
    const int t = blockIdx.x;       // token 0..16383
    const int d = threadIdx.x;      // 0..255
    const int idx = g_idx[t];
    const float v  = __ldg(cb + (size_t)idx * DD + d);
    const float xe = __ldg(x  + (size_t)t   * DD + d);
    const size_t BND = (size_t)M_TOK * DD;
    out[(size_t)t * DD + d]            = v;    // x_recon
    out[BND + (size_t)t * DD + d]      = xe;   // z_e
    out[2 * BND + (size_t)t * DD + d]  = v;    // z_q
    if (d == 0) out[3 * BND + t] = (float)idx; // indices (cast to out dtype)
}

// ---------------------------------------------------------------------------
extern "C" void kernel_launch(void* const* d_in, const int* in_sizes, int n_in,
                              void* d_out, int out_size) {
    const float* x  = (const float*)d_in[0];   // (8,2048,256) f32
    const float* cb = (const float*)d_in[1];   // (8192,256)  f32
    float* out = (float*)d_out;

    // 1) codebook squared norms: 8192 warps
    c2_kernel<<<KK / 8, 256>>>(cb);

    // 2) fused distance + argmin
    const int smem_bytes = (BM * DD + BN * BS_STRIDE) * sizeof(float); // 82944
    cudaFuncSetAttribute(vq_argmin_kernel,
                         cudaFuncAttributeMaxDynamicSharedMemorySize, smem_bytes);
    vq_argmin_kernel<<<M_TOK / BM, THREADS, smem_bytes>>>(x, cb);

    // 3) outputs
    scatter_kernel<<<M_TOK, DD>>>(x, cb, out);
}

// round 9
// speedup vs baseline: 1.9824x; 1.9824x over previous
#include <cuda_runtime.h>
#include <cuda_fp16.h>

#define BB 8
#define NN 2048
#define DD 256
#define KK 8192
#define M_TOK (BB*NN)          // 16384

#define M_TILE 128
#define N_TILE 128
#define NT (KK / N_TILE)       // 64 n-tiles
#define NCHUNK (NT * 8)        // 512 k-chunks of 32 halves (8 per n-tile)
#define THREADS 256

#define LDA 264                // A smem stride in halves (528 B, conflict-free ldmatrix)
#define LDB 40                 // B smem stride in halves (80 B, conflict-free ldmatrix)

// smem byte offsets
#define SM_AHI 0
#define SM_ALO 67584                    // 128*264*2
#define SM_B   135168                   // 2 stages x 20480 (hi 10240 | lo 10240)
#define SM_C2  176128                   // 8192 floats
#define SMEM_TOTAL 208896

__device__ __align__(1024) __half g_cb_hi[KK*DD];
__device__ __align__(1024) __half g_cb_lo[KK*DD];
__device__ float g_c2[KK];
__device__ int   g_idx[M_TOK];

// ---- PTX helpers -----------------------------------------------------------
__device__ __forceinline__ void ldsm4(unsigned& r0, unsigned& r1, unsigned& r2,
                                      unsigned& r3, unsigned addr) {
    asm volatile("ldmatrix.sync.aligned.m8n8.x4.shared.b16 {%0,%1,%2,%3}, [%4];"
                 : "=r"(r0), "=r"(r1), "=r"(r2), "=r"(r3) : "r"(addr));
}
__device__ __forceinline__ void mma16816(float* c, unsigned a0, unsigned a1,
                                         unsigned a2, unsigned a3,
                                         unsigned b0, unsigned b1) {
    asm volatile("mma.sync.aligned.m16n8k16.row.col.f32.f16.f16.f32 "
                 "{%0,%1,%2,%3}, {%4,%5,%6,%7}, {%8,%9}, {%0,%1,%2,%3};"
                 : "+f"(c[0]), "+f"(c[1]), "+f"(c[2]), "+f"(c[3])
                 : "r"(a0), "r"(a1), "r"(a2), "r"(a3), "r"(b0), "r"(b1));
}
__device__ __forceinline__ void cp16(unsigned dst, const void* src) {
    asm volatile("cp.async.cg.shared.global [%0], [%1], 16;"
                 :: "r"(dst), "l"((unsigned long long)__cvta_generic_to_global(src))
                 : "memory");
}
#define CP_COMMIT() asm volatile("cp.async.commit_group;" ::: "memory")
#define CP_WAIT1()  asm volatile("cp.async.wait_group 1;" ::: "memory")

// ---------------------------------------------------------------------------
// Kernel 1: codebook fp16 hi/lo split + squared norms. One block per code row.
// ---------------------------------------------------------------------------
__global__ void cvt_cb_kernel(const float* __restrict__ cb) {
    const int row = blockIdx.x, d = threadIdx.x;
    float v = cb[row * DD + d];
    __half h = __float2half_rn(v);
    __half l = __float2half_rn(v - __half2float(h));
    g_cb_hi[row * DD + d] = h;
    g_cb_lo[row * DD + d] = l;
    float s = v * v;
    #pragma unroll
    for (int o = 16; o; o >>= 1) s += __shfl_xor_sync(0xffffffffu, s, o);
    __shared__ float ws[8];
    if ((threadIdx.x & 31) == 0) ws[threadIdx.x >> 5] = s;
    __syncthreads();
    if (threadIdx.x == 0) {
        float t = 0.f;
        #pragma unroll
        for (int w = 0; w < 8; w++) t += ws[w];
        g_c2[row] = t;
    }
}

// ---------------------------------------------------------------------------
// Kernel 2: HMMA fused distance + argmin (fp16 3-product precision split)
// ---------------------------------------------------------------------------
__global__ void __launch_bounds__(THREADS, 1)
vq_mma_kernel(const float* __restrict__ x) {
    extern __shared__ char smem[];
    const unsigned sb = (unsigned)__cvta_generic_to_shared(smem);
    const int tid  = threadIdx.x;
    const int wid  = tid >> 5;
    const int lane = tid & 31;
    const int wm   = wid >> 2;          // 0..1  (64 rows each)
    const int wn   = wid & 3;           // 0..3  (32 cols each)
    const int rowBase = blockIdx.x * M_TILE;

    // ---- load A tile: 128 tokens x 256 d, fp32 -> fp16 hi/lo in padded smem
    for (int r = 0; r < 32; r++) {
        int i   = r * THREADS + tid;         // float4 index, 8192 total
        int tok = i >> 6, dg = i & 63;
        float4 v = __ldg((const float4*)(x + (size_t)(rowBase + tok) * DD + dg * 4));
        __half h0 = __float2half_rn(v.x), h1 = __float2half_rn(v.y);
        __half h2 = __float2half_rn(v.z), h3 = __float2half_rn(v.w);
        __half l0 = __float2half_rn(v.x - __half2float(h0));
        __half l1 = __float2half_rn(v.y - __half2float(h1));
        __half l2 = __float2half_rn(v.z - __half2float(h2));
        __half l3 = __float2half_rn(v.w - __half2float(h3));
        unsigned off = (unsigned)(tok * LDA + dg * 4) * 2;
        *(__half2*)(smem + SM_AHI + off)     = __halves2half2(h0, h1);
        *(__half2*)(smem + SM_AHI + off + 4) = __halves2half2(h2, h3);
        *(__half2*)(smem + SM_ALO + off)     = __halves2half2(l0, l1);
        *(__half2*)(smem + SM_ALO + off + 4) = __halves2half2(l2, l3);
    }
    // c2 into smem
    for (int i = tid; i < KK; i += THREADS)
        *(float*)(smem + SM_C2 + i * 4) = g_c2[i];
    __syncthreads();

    // per-thread ldmatrix base offsets
    const unsigned aoff = ((unsigned)((wm * 64 + (lane & 15)) * LDA) + (lane >> 4) * 8) * 2;
    const unsigned boff = ((unsigned)((wn * 32 + (lane >> 4) * 8 + (lane & 7)) * LDB)
                           + ((lane >> 3) & 1) * 8) * 2;

    float acc[4][4][4];
    #pragma unroll
    for (int mi = 0; mi < 4; mi++)            // zero accumulators before first tile
        #pragma unroll
        for (int ni = 0; ni < 4; ni++)
            #pragma unroll
            for (int q = 0; q < 4; q++) acc[mi][ni][q] = 0.f;

    float best[4][2];
    int   bidx[4][2];
    #pragma unroll
    for (int mi = 0; mi < 4; mi++)
        #pragma unroll
        for (int rr = 0; rr < 2; rr++) { best[mi][rr] = 3.4e38f; bidx[mi][rr] = 0; }

    // prefetch chunk 0 into stage 0
    {
        const int nt = 0, kc = 0;
        #pragma unroll
        for (int rep = 0; rep < 4; rep++) {
            int idx = rep * THREADS + tid;               // 1024 x 16B
            int hl = idx >> 9, r = (idx >> 2) & 127, cc = idx & 3;
            const __half* src = (hl ? g_cb_lo : g_cb_hi)
                              + ((size_t)(nt * N_TILE + r) * DD + kc * 32 + cc * 8);
            cp16(sb + SM_B + hl * 10240 + r * (LDB * 2) + cc * 16, src);
        }
    }
    CP_COMMIT();

    for (int g = 0; g < NCHUNK; g++) {
        // prefetch chunk g+1 into stage (g+1)&1
        if (g + 1 < NCHUNK) {
            const int nt = (g + 1) >> 3, kc = (g + 1) & 7, st = (g + 1) & 1;
            #pragma unroll
            for (int rep = 0; rep < 4; rep++) {
                int idx = rep * THREADS + tid;
                int hl = idx >> 9, r = (idx >> 2) & 127, cc = idx & 3;
                const __half* src = (hl ? g_cb_lo : g_cb_hi)
                                  + ((size_t)(nt * N_TILE + r) * DD + kc * 32 + cc * 8);
                cp16(sb + SM_B + st * 20480 + hl * 10240 + r * (LDB * 2) + cc * 16, src);
            }
        }
        CP_COMMIT();
        CP_WAIT1();
        __syncthreads();

        const unsigned bbase = sb + SM_B + (unsigned)(g & 1) * 20480;
        const unsigned kb2 = (unsigned)((g & 7) * 32) * 2;    // A k-chunk byte offset

        #pragma unroll
        for (int k16 = 0; k16 < 2; k16++) {
            const unsigned kaA = kb2 + (unsigned)k16 * 32;    // A: full-K resident
            const unsigned kaB = (unsigned)k16 * 32;          // FIX: B stage is chunk-relative
            unsigned ah[4][4], al[4][4], bh[2][4], bl[2][4];
            #pragma unroll
            for (int mi = 0; mi < 4; mi++) {
                ldsm4(ah[mi][0], ah[mi][1], ah[mi][2], ah[mi][3],
                      sb + SM_AHI + aoff + (unsigned)(mi * 16 * LDA * 2) + kaA);
                ldsm4(al[mi][0], al[mi][1], al[mi][2], al[mi][3],
                      sb + SM_ALO + aoff + (unsigned)(mi * 16 * LDA * 2) + kaA);
            }
            #pragma unroll
            for (int p = 0; p < 2; p++) {
                ldsm4(bh[p][0], bh[p][1], bh[p][2], bh[p][3],
                      bbase + boff + (unsigned)(p * 16 * LDB * 2) + kaB);
                ldsm4(bl[p][0], bl[p][1], bl[p][2], bl[p][3],
                      bbase + 10240 + boff + (unsigned)(p * 16 * LDB * 2) + kaB);
            }
            #pragma unroll
            for (int mi = 0; mi < 4; mi++)
                #pragma unroll
                for (int ni = 0; ni < 4; ni++) {
                    unsigned b0h = bh[ni >> 1][(ni & 1) * 2], b1h = bh[ni >> 1][(ni & 1) * 2 + 1];
                    unsigned b0l = bl[ni >> 1][(ni & 1) * 2], b1l = bl[ni >> 1][(ni & 1) * 2 + 1];
                    mma16816(acc[mi][ni], ah[mi][0], ah[mi][1], ah[mi][2], ah[mi][3], b0h, b1h);
                    mma16816(acc[mi][ni], ah[mi][0], ah[mi][1], ah[mi][2], ah[mi][3], b0l, b1l);
                    mma16816(acc[mi][ni], al[mi][0], al[mi][1], al[mi][2], al[mi][3], b0h, b1h);
                }
        }

        if ((g & 7) == 7) {
            // drain: s = c2 - 2*cross, running argmin; then zero accumulators
            const int nt = g >> 3;
            #pragma unroll
            for (int ni = 0; ni < 4; ni++) {
                int col = nt * N_TILE + wn * 32 + ni * 8 + (lane & 3) * 2;
                float c20 = *(float*)(smem + SM_C2 + col * 4);
                float c21 = *(float*)(smem + SM_C2 + (col + 1) * 4);
                #pragma unroll
                for (int mi = 0; mi < 4; mi++) {
                    #pragma unroll
                    for (int rr = 0; rr < 2; rr++) {
                        float s0 = fmaf(-2.0f, acc[mi][ni][rr * 2],     c20);
                        float s1 = fmaf(-2.0f, acc[mi][ni][rr * 2 + 1], c21);
                        if (s0 < best[mi][rr]) { best[mi][rr] = s0; bidx[mi][rr] = col; }
                        if (s1 < best[mi][rr]) { best[mi][rr] = s1; bidx[mi][rr] = col + 1; }
                        acc[mi][ni][rr * 2]     = 0.f;
                        acc[mi][ni][rr * 2 + 1] = 0.f;
                    }
                }
            }
        }
        __syncthreads();   // protect stage g&1 before next prefetch overwrites it
    }

    // ---- cross-thread argmin reduce (16 candidates per row), reuse B region
    float* rv = (float*)(smem + SM_B);             // [128][16]
    int*   ri = (int*)  (smem + SM_B + 128 * 16 * 4);
    const int cand = wn * 4 + (lane & 3);
    #pragma unroll
    for (int mi = 0; mi < 4; mi++)
        #pragma unroll
        for (int rr = 0; rr < 2; rr++) {
            int row = wm * 64 + mi * 16 + rr * 8 + (lane >> 2);
            rv[row * 16 + cand] = best[mi][rr];
            ri[row * 16 + cand] = bidx[mi][rr];
        }
    __syncthreads();
    if (tid < M_TILE) {
        float bv = rv[tid * 16];
        int   bi = ri[tid * 16];
        #pragma unroll
        for (int t = 1; t < 16; t++) {
            float v  = rv[tid * 16 + t];
            int   ii = ri[tid * 16 + t];
            if (v < bv || (v == bv && ii < bi)) { bv = v; bi = ii; }
        }
        g_idx[rowBase + tid] = bi;
    }
}

// ---------------------------------------------------------------------------
// Kernel 3: outputs. Layout: [x_recon | z_e | z_q | indices(float)]
// ---------------------------------------------------------------------------
__global__ void scatter_kernel(const float* __restrict__ x,
                               const float* __restrict__ cb,
                               float* __restrict__ out) {
    const int t = blockIdx.x;
    const int d = threadIdx.x;
    const int idx = g_idx[t];
    const float v  = __ldg(cb + (size_t)idx * DD + d);
    const float xe = __ldg(x  + (size_t)t   * DD + d);
    const size_t BND = (size_t)M_TOK * DD;
    out[(size_t)t * DD + d]           = v;
    out[BND + (size_t)t * DD + d]     = xe;
    out[2 * BND + (size_t)t * DD + d] = v;
    if (d == 0) out[3 * BND + t] = (float)idx;
}

// ---------------------------------------------------------------------------
extern "C" void kernel_launch(void* const* d_in, const int* in_sizes, int n_in,
                              void* d_out, int out_size) {
    const float* x  = (const float*)d_in[0];
    const float* cb = (const float*)d_in[1];
    float* out = (float*)d_out;

    cvt_cb_kernel<<<KK, DD>>>(cb);

    cudaFuncSetAttribute(vq_mma_kernel,
                         cudaFuncAttributeMaxDynamicSharedMemorySize, SMEM_TOTAL);
    vq_mma_kernel<<<M_TOK / M_TILE, THREADS, SMEM_TOTAL>>>(x);

    scatter_kernel<<<M_TOK, DD>>>(x, cb, out);
}

// round 10
// speedup vs baseline: 2.8306x; 1.4279x over previous
#include <cuda_runtime.h>
#include <cuda_fp16.h>

#define BB 8
#define NN 2048
#define DD 256
#define KK 8192
#define M_TOK (BB*NN)          // 16384

#define M_TILE 64
#define N_TILE 128
#define NT (KK / N_TILE)       // 64 n-tiles
#define NCHUNK (NT * 8)        // 512 k-chunks of 32 halves (8 per n-tile)
#define THREADS 256

#define LDA 264                // A smem stride in halves (528 B, conflict-free ldmatrix)
#define LDB 40                 // B smem stride in halves (80 B, conflict-free ldmatrix)

// smem byte offsets (per-CTA total 108544 B -> 2 CTAs/SM)
#define SM_AHI 0
#define SM_ALO 33792                    // 64*264*2
#define SM_B   67584                    // 2 stages x 20480 (hi 10240 | lo 10240)
#define SMEM_TOTAL 108544

__device__ __align__(1024) __half g_cb_hi[KK*DD];
__device__ __align__(1024) __half g_cb_lo[KK*DD];
__device__ float g_c2[KK];
__device__ int   g_idx[M_TOK];

// ---- PTX helpers -----------------------------------------------------------
__device__ __forceinline__ void ldsm4(unsigned& r0, unsigned& r1, unsigned& r2,
                                      unsigned& r3, unsigned addr) {
    asm volatile("ldmatrix.sync.aligned.m8n8.x4.shared.b16 {%0,%1,%2,%3}, [%4];"
                 : "=r"(r0), "=r"(r1), "=r"(r2), "=r"(r3) : "r"(addr));
}
__device__ __forceinline__ void mma16816(float* c, unsigned a0, unsigned a1,
                                         unsigned a2, unsigned a3,
                                         unsigned b0, unsigned b1) {
    asm volatile("mma.sync.aligned.m16n8k16.row.col.f32.f16.f16.f32 "
                 "{%0,%1,%2,%3}, {%4,%5,%6,%7}, {%8,%9}, {%0,%1,%2,%3};"
                 : "+f"(c[0]), "+f"(c[1]), "+f"(c[2]), "+f"(c[3])
                 : "r"(a0), "r"(a1), "r"(a2), "r"(a3), "r"(b0), "r"(b1));
}
__device__ __forceinline__ void cp16(unsigned dst, const void* src) {
    asm volatile("cp.async.cg.shared.global [%0], [%1], 16;"
                 :: "r"(dst), "l"((unsigned long long)__cvta_generic_to_global(src))
                 : "memory");
}
#define CP_COMMIT() asm volatile("cp.async.commit_group;" ::: "memory")
#define CP_WAIT1()  asm volatile("cp.async.wait_group 1;" ::: "memory")

// ---------------------------------------------------------------------------
// Kernel 1: codebook fp16 hi/lo split + squared norms. One block per code row.
// ---------------------------------------------------------------------------
__global__ void cvt_cb_kernel(const float* __restrict__ cb) {
    const int row = blockIdx.x, d = threadIdx.x;
    float v = cb[row * DD + d];
    __half h = __float2half_rn(v);
    __half l = __float2half_rn(v - __half2float(h));
    g_cb_hi[row * DD + d] = h;
    g_cb_lo[row * DD + d] = l;
    float s = v * v;
    #pragma unroll
    for (int o = 16; o; o >>= 1) s += __shfl_xor_sync(0xffffffffu, s, o);
    __shared__ float ws[8];
    if ((threadIdx.x & 31) == 0) ws[threadIdx.x >> 5] = s;
    __syncthreads();
    if (threadIdx.x == 0) {
        float t = 0.f;
        #pragma unroll
        for (int w = 0; w < 8; w++) t += ws[w];
        g_c2[row] = t;
    }
}

// ---------------------------------------------------------------------------
// Kernel 2: HMMA fused distance + argmin (fp16 3-product precision split)
//   M_TILE=64, 106KB smem -> 2 CTAs/SM (4 warps/SMSP) for latency hiding.
// ---------------------------------------------------------------------------
__global__ void __launch_bounds__(THREADS, 2)
vq_mma_kernel(const float* __restrict__ x) {
    extern __shared__ char smem[];
    const unsigned sb = (unsigned)__cvta_generic_to_shared(smem);
    const int tid  = threadIdx.x;
    const int wid  = tid >> 5;
    const int lane = tid & 31;
    const int wm   = wid >> 2;          // 0..1  (32 rows each)
    const int wn   = wid & 3;           // 0..3  (32 cols each)
    const int rowBase = blockIdx.x * M_TILE;

    // ---- load A tile: 64 tokens x 256 d, fp32 -> fp16 hi/lo in padded smem
    for (int r = 0; r < 16; r++) {
        int i   = r * THREADS + tid;         // float4 index, 4096 total
        int tok = i >> 6, dg = i & 63;
        float4 v = __ldg((const float4*)(x + (size_t)(rowBase + tok) * DD + dg * 4));
        __half h0 = __float2half_rn(v.x), h1 = __float2half_rn(v.y);
        __half h2 = __float2half_rn(v.z), h3 = __float2half_rn(v.w);
        __half l0 = __float2half_rn(v.x - __half2float(h0));
        __half l1 = __float2half_rn(v.y - __half2float(h1));
        __half l2 = __float2half_rn(v.z - __half2float(h2));
        __half l3 = __float2half_rn(v.w - __half2float(h3));
        unsigned off = (unsigned)(tok * LDA + dg * 4) * 2;
        *(__half2*)(smem + SM_AHI + off)     = __halves2half2(h0, h1);
        *(__half2*)(smem + SM_AHI + off + 4) = __halves2half2(h2, h3);
        *(__half2*)(smem + SM_ALO + off)     = __halves2half2(l0, l1);
        *(__half2*)(smem + SM_ALO + off + 4) = __halves2half2(l2, l3);
    }
    __syncthreads();

    // per-thread ldmatrix base offsets
    const unsigned aoff = ((unsigned)((wm * 32 + (lane & 15)) * LDA) + (lane >> 4) * 8) * 2;
    const unsigned boff = ((unsigned)((wn * 32 + (lane >> 4) * 8 + (lane & 7)) * LDB)
                           + ((lane >> 3) & 1) * 8) * 2;

    float acc[2][4][4];
    #pragma unroll
    for (int mi = 0; mi < 2; mi++)
        #pragma unroll
        for (int ni = 0; ni < 4; ni++)
            #pragma unroll
            for (int q = 0; q < 4; q++) acc[mi][ni][q] = 0.f;

    float best[2][2];
    int   bidx[2][2];
    #pragma unroll
    for (int mi = 0; mi < 2; mi++)
        #pragma unroll
        for (int rr = 0; rr < 2; rr++) { best[mi][rr] = 3.4e38f; bidx[mi][rr] = 0; }

    // prefetch chunk 0 into stage 0
    {
        #pragma unroll
        for (int rep = 0; rep < 4; rep++) {
            int idx = rep * THREADS + tid;               // 1024 x 16B
            int hl = idx >> 9, r = (idx >> 2) & 127, cc = idx & 3;
            const __half* src = (hl ? g_cb_lo : g_cb_hi) + ((size_t)r * DD + cc * 8);
            cp16(sb + SM_B + hl * 10240 + r * (LDB * 2) + cc * 16, src);
        }
    }
    CP_COMMIT();

    for (int g = 0; g < NCHUNK; g++) {
        // prefetch chunk g+1 into stage (g+1)&1
        if (g + 1 < NCHUNK) {
            const int nt = (g + 1) >> 3, kc = (g + 1) & 7, st = (g + 1) & 1;
            #pragma unroll
            for (int rep = 0; rep < 4; rep++) {
                int idx = rep * THREADS + tid;
                int hl = idx >> 9, r = (idx >> 2) & 127, cc = idx & 3;
                const __half* src = (hl ? g_cb_lo : g_cb_hi)
                                  + ((size_t)(nt * N_TILE + r) * DD + kc * 32 + cc * 8);
                cp16(sb + SM_B + st * 20480 + hl * 10240 + r * (LDB * 2) + cc * 16, src);
            }
        }
        CP_COMMIT();
        CP_WAIT1();
        __syncthreads();

        const unsigned bbase = sb + SM_B + (unsigned)(g & 1) * 20480;
        const unsigned kb2 = (unsigned)((g & 7) * 32) * 2;    // A k-chunk byte offset

        #pragma unroll
        for (int k16 = 0; k16 < 2; k16++) {
            const unsigned kaA = kb2 + (unsigned)k16 * 32;    // A: full-K resident
            const unsigned kaB = (unsigned)k16 * 32;          // B: stage chunk-relative
            unsigned ah[2][4], al[2][4], bh[2][4], bl[2][4];
            #pragma unroll
            for (int mi = 0; mi < 2; mi++) {
                ldsm4(ah[mi][0], ah[mi][1], ah[mi][2], ah[mi][3],
                      sb + SM_AHI + aoff + (unsigned)(mi * 16 * LDA * 2) + kaA);
                ldsm4(al[mi][0], al[mi][1], al[mi][2], al[mi][3],
                      sb + SM_ALO + aoff + (unsigned)(mi * 16 * LDA * 2) + kaA);
            }
            #pragma unroll
            for (int p = 0; p < 2; p++) {
                ldsm4(bh[p][0], bh[p][1], bh[p][2], bh[p][3],
                      bbase + boff + (unsigned)(p * 16 * LDB * 2) + kaB);
                ldsm4(bl[p][0], bl[p][1], bl[p][2], bl[p][3],
                      bbase + 10240 + boff + (unsigned)(p * 16 * LDB * 2) + kaB);
            }
            // pass-major emission: 8 independent chains per pass
            #pragma unroll
            for (int mi = 0; mi < 2; mi++)
                #pragma unroll
                for (int ni = 0; ni < 4; ni++)
                    mma16816(acc[mi][ni], ah[mi][0], ah[mi][1], ah[mi][2], ah[mi][3],
                             bh[ni >> 1][(ni & 1) * 2], bh[ni >> 1][(ni & 1) * 2 + 1]);
            #pragma unroll
            for (int mi = 0; mi < 2; mi++)
                #pragma unroll
                for (int ni = 0; ni < 4; ni++)
                    mma16816(acc[mi][ni], ah[mi][0], ah[mi][1], ah[mi][2], ah[mi][3],
                             bl[ni >> 1][(ni & 1) * 2], bl[ni >> 1][(ni & 1) * 2 + 1]);
            #pragma unroll
            for (int mi = 0; mi < 2; mi++)
                #pragma unroll
                for (int ni = 0; ni < 4; ni++)
                    mma16816(acc[mi][ni], al[mi][0], al[mi][1], al[mi][2], al[mi][3],
                             bh[ni >> 1][(ni & 1) * 2], bh[ni >> 1][(ni & 1) * 2 + 1]);
        }

        if ((g & 7) == 7) {
            // drain: s = c2 - 2*cross, running argmin; then zero accumulators
            const int nt = g >> 3;
            #pragma unroll
            for (int ni = 0; ni < 4; ni++) {
                int col = nt * N_TILE + wn * 32 + ni * 8 + (lane & 3) * 2;
                float c20 = __ldg(&g_c2[col]);
                float c21 = __ldg(&g_c2[col + 1]);
                #pragma unroll
                for (int mi = 0; mi < 2; mi++) {
                    #pragma unroll
                    for (int rr = 0; rr < 2; rr++) {
                        float s0 = fmaf(-2.0f, acc[mi][ni][rr * 2],     c20);
                        float s1 = fmaf(-2.0f, acc[mi][ni][rr * 2 + 1], c21);
                        if (s0 < best[mi][rr]) { best[mi][rr] = s0; bidx[mi][rr] = col; }
                        if (s1 < best[mi][rr]) { best[mi][rr] = s1; bidx[mi][rr] = col + 1; }
                        acc[mi][ni][rr * 2]     = 0.f;
                        acc[mi][ni][rr * 2 + 1] = 0.f;
                    }
                }
            }
        }
        __syncthreads();   // protect stage g&1 before next prefetch overwrites it
    }

    // ---- cross-thread argmin reduce (16 candidates per row), reuse B region
    float* rv = (float*)(smem + SM_B);             // [64][16]
    int*   ri = (int*)  (smem + SM_B + 64 * 16 * 4);
    const int cand = wn * 4 + (lane & 3);
    #pragma unroll
    for (int mi = 0; mi < 2; mi++)
        #pragma unroll
        for (int rr = 0; rr < 2; rr++) {
            int row = wm * 32 + mi * 16 + rr * 8 + (lane >> 2);
            rv[row * 16 + cand] = best[mi][rr];
            ri[row * 16 + cand] = bidx[mi][rr];
        }
    __syncthreads();
    if (tid < M_TILE) {
        float bv = rv[tid * 16];
        int   bi = ri[tid * 16];
        #pragma unroll
        for (int t = 1; t < 16; t++) {
            float v  = rv[tid * 16 + t];
            int   ii = ri[tid * 16 + t];
            if (v < bv || (v == bv && ii < bi)) { bv = v; bi = ii; }
        }
        g_idx[rowBase + tid] = bi;
    }
}

// ---------------------------------------------------------------------------
// Kernel 3: outputs. Layout: [x_recon | z_e | z_q | indices(float)]
// ---------------------------------------------------------------------------
__global__ void scatter_kernel(const float* __restrict__ x,
                               const float* __restrict__ cb,
                               float* __restrict__ out) {
    const int t = blockIdx.x;
    const int d = threadIdx.x;
    const int idx = g_idx[t];
    const float v  = __ldg(cb + (size_t)idx * DD + d);
    const float xe = __ldg(x  + (size_t)t   * DD + d);
    const size_t BND = (size_t)M_TOK * DD;
    out[(size_t)t * DD + d]           = v;
    out[BND + (size_t)t * DD + d]     = xe;
    out[2 * BND + (size_t)t * DD + d] = v;
    if (d == 0) out[3 * BND + t] = (float)idx;
}

// ---------------------------------------------------------------------------
extern "C" void kernel_launch(void* const* d_in, const int* in_sizes, int n_in,
                              void* d_out, int out_size) {
    const float* x  = (const float*)d_in[0];
    const float* cb = (const float*)d_in[1];
    float* out = (float*)d_out;

    cvt_cb_kernel<<<KK, DD>>>(cb);

    cudaFuncSetAttribute(vq_mma_kernel,
                         cudaFuncAttributeMaxDynamicSharedMemorySize, SMEM_TOTAL);
    vq_mma_kernel<<<M_TOK / M_TILE, THREADS, SMEM_TOTAL>>>(x);

    scatter_kernel<<<M_TOK, DD>>>(x, cb, out);
}